// round 4
// baseline (speedup 1.0000x reference)
#include <cuda_runtime.h>
#include <cstdint>
#include <cmath>

// ---------------------------------------------------------------------------
// Problem constants (fixed by setup_inputs)
// ---------------------------------------------------------------------------
#define BATCH 32768
#define VDIM  1024
#define HDIM  128
#define NITER 4

// Modern JAX default: jax_threefry_partitionable = True.
// If bench shows O(1) rel_err, flip this to 0 (legacy split-halves threefry).
#define TF_PARTITIONABLE 1

// ---------------------------------------------------------------------------
// Threefry-2x32 (exact JAX rounds)
// ---------------------------------------------------------------------------
__host__ __device__ __forceinline__ uint32_t rotl32(uint32_t v, int s) {
    return (v << s) | (v >> (32 - s));
}

__host__ __device__ inline void threefry2x32(uint32_t k0, uint32_t k1,
                                             uint32_t x0, uint32_t x1,
                                             uint32_t &o0, uint32_t &o1) {
    const uint32_t k2 = k0 ^ k1 ^ 0x1BD11BDAu;
    x0 += k0; x1 += k1;
#define TF_ROUND(r) { x0 += x1; x1 = rotl32(x1, (r)); x1 ^= x0; }
    TF_ROUND(13) TF_ROUND(15) TF_ROUND(26) TF_ROUND(6)
    x0 += k1; x1 += k2 + 1u;
    TF_ROUND(17) TF_ROUND(29) TF_ROUND(16) TF_ROUND(24)
    x0 += k2; x1 += k0 + 2u;
    TF_ROUND(13) TF_ROUND(15) TF_ROUND(26) TF_ROUND(6)
    x0 += k0; x1 += k1 + 3u;
    TF_ROUND(17) TF_ROUND(29) TF_ROUND(16) TF_ROUND(24)
    x0 += k1; x1 += k2 + 4u;
    TF_ROUND(13) TF_ROUND(15) TF_ROUND(26) TF_ROUND(6)
    x0 += k2; x1 += k0 + 5u;
#undef TF_ROUND
    o0 = x0; o1 = x1;
}

// Per-element uniform bits, matching jax.random._random_bits on a flat array.
// Partitionable path (bit_width=32): bits = y0 ^ y1 of threefry(key, hi, lo)
// where (hi, lo) is the 64-bit flat index (hi = 0 for our sizes).
__device__ __forceinline__ uint32_t jax_bits(uint32_t key0, uint32_t key1,
                                             uint32_t idx, uint32_t total) {
    uint32_t y0, y1;
#if TF_PARTITIONABLE
    (void)total;
    threefry2x32(key0, key1, 0u, idx, y0, y1);
    return y0 ^ y1;
#else
    uint32_t half = total >> 1;
    if (idx < half) {
        threefry2x32(key0, key1, idx, idx + half, y0, y1);
        return y0;
    } else {
        threefry2x32(key0, key1, idx - half, idx, y0, y1);
        return y1;
    }
#endif
}

// ---------------------------------------------------------------------------
// Fused GEMM -> sigmoid -> Bernoulli-sample kernel.
//   out[m, n] = bernoulli( sigmoid( sum_k A[m,k] * Wmat(k,n) + bias[n] ) )
// BTRANS=true : Wmat stored [N, K] (row-major) -> used for  W @ v   (H-step)
// BTRANS=false: Wmat stored [K, N] (row-major) -> used for  W^T @ h (V-step)
// ---------------------------------------------------------------------------
template <int BM, int BN, int BK, int TM, int TN, bool BTRANS>
__global__ __launch_bounds__(256)
void gemm_sigmoid_sample(const float* __restrict__ A,
                         const float* __restrict__ Wmat,
                         const float* __restrict__ bias,
                         float* __restrict__ out,
                         int N, int K,
                         uint32_t key0, uint32_t key1, uint32_t total) {
    constexpr int THREADS = (BM / TM) * (BN / TN);
    static_assert(THREADS == 256, "config must give 256 threads");

    __shared__ float As[BK][BM + 1];
    __shared__ float Bs[BK][BN + 1];

    const int tid = threadIdx.x;
    const int m0 = blockIdx.x * BM;
    const int n0 = blockIdx.y * BN;
    const int tx = tid % (BN / TN);
    const int ty = tid / (BN / TN);

    float acc[TM][TN];
#pragma unroll
    for (int i = 0; i < TM; i++)
#pragma unroll
        for (int j = 0; j < TN; j++) acc[i][j] = 0.f;

    for (int k0 = 0; k0 < K; k0 += BK) {
        // ---- load A tile (coalesced float4 along K, store transposed) ----
        constexpr int A4 = BM * BK / 4;
#pragma unroll
        for (int it = 0; it < A4 / THREADS; it++) {
            int id  = tid + it * THREADS;
            int row = id / (BK / 4);
            int c4  = id % (BK / 4);
            float4 v = *reinterpret_cast<const float4*>(
                A + (size_t)(m0 + row) * K + k0 + c4 * 4);
            As[c4 * 4 + 0][row] = v.x;
            As[c4 * 4 + 1][row] = v.y;
            As[c4 * 4 + 2][row] = v.z;
            As[c4 * 4 + 3][row] = v.w;
        }
        // ---- load B tile ----
        if (BTRANS) {
            constexpr int B4 = BN * BK / 4;
#pragma unroll
            for (int it = 0; it < B4 / THREADS; it++) {
                int id  = tid + it * THREADS;
                int row = id / (BK / 4);   // n
                int c4  = id % (BK / 4);
                float4 v = *reinterpret_cast<const float4*>(
                    Wmat + (size_t)(n0 + row) * K + k0 + c4 * 4);
                Bs[c4 * 4 + 0][row] = v.x;
                Bs[c4 * 4 + 1][row] = v.y;
                Bs[c4 * 4 + 2][row] = v.z;
                Bs[c4 * 4 + 3][row] = v.w;
            }
        } else {
            constexpr int B4 = BN * BK / 4;
#pragma unroll
            for (int it = 0; it < B4 / THREADS; it++) {
                int id  = tid + it * THREADS;
                int row = id / (BN / 4);   // k
                int c4  = id % (BN / 4);
                float4 v = *reinterpret_cast<const float4*>(
                    Wmat + (size_t)(k0 + row) * N + n0 + c4 * 4);
                Bs[row][c4 * 4 + 0] = v.x;
                Bs[row][c4 * 4 + 1] = v.y;
                Bs[row][c4 * 4 + 2] = v.z;
                Bs[row][c4 * 4 + 3] = v.w;
            }
        }
        __syncthreads();

        // ---- compute (two-level accumulation: per-tile partial) ----
        float part[TM][TN];
#pragma unroll
        for (int i = 0; i < TM; i++)
#pragma unroll
            for (int j = 0; j < TN; j++) part[i][j] = 0.f;

#pragma unroll
        for (int kk = 0; kk < BK; kk++) {
            float a[TM], b[TN];
#pragma unroll
            for (int i = 0; i < TM; i++) a[i] = As[kk][ty * TM + i];
#pragma unroll
            for (int j = 0; j < TN; j++) b[j] = Bs[kk][tx * TN + j];
#pragma unroll
            for (int i = 0; i < TM; i++)
#pragma unroll
                for (int j = 0; j < TN; j++) part[i][j] += a[i] * b[j];
        }
#pragma unroll
        for (int i = 0; i < TM; i++)
#pragma unroll
            for (int j = 0; j < TN; j++) acc[i][j] += part[i][j];
        __syncthreads();
    }

    // ---- epilogue: sigmoid + threefry-bernoulli ----
#pragma unroll
    for (int i = 0; i < TM; i++) {
#pragma unroll
        for (int j = 0; j < TN; j++) {
            int m = m0 + ty * TM + i;
            int n = n0 + tx * TN + j;
            float x = acc[i][j] + __ldg(bias + n);
            float p = 1.f / (1.f + expf(-x));
            uint32_t idx = (uint32_t)m * (uint32_t)N + (uint32_t)n;
            uint32_t bits = jax_bits(key0, key1, idx, total);
            float u = __uint_as_float((bits >> 9) | 0x3f800000u) - 1.f;
            float s;
            if (fabsf(u - p) > 1e-4f) {
                // fast path: decision unaffected by fp32 sigmoid error
                s = (u < p) ? 1.f : 0.f;
            } else {
                // rare slow path: re-decide with fp64 sigmoid, rounded to fp32
                double pd = 1.0 / (1.0 + exp(-(double)x));
                s = (u < (float)pd) ? 1.f : 0.f;
            }
            out[idx] = s;
        }
    }
}

// ---------------------------------------------------------------------------
// Host-side JAX key derivation
// ---------------------------------------------------------------------------
struct Key { uint32_t k0, k1; };

static inline Key tf_key(Key k, uint32_t lo) {
#if TF_PARTITIONABLE
    Key r;
    threefry2x32(k.k0, k.k1, 0u, lo, r.k0, r.k1);
    return r;
#else
    (void)k; (void)lo;
    return Key{0, 0}; // filled by legacy path below
#endif
}

#if !TF_PARTITIONABLE
// legacy split(key, n): counts 0..2n-1, halves paired, reshape(n,2)
static void legacy_split(Key k, int n, Key* out) {
    uint32_t buf[32];
    for (int i = 0; i < n; i++) {
        uint32_t y0, y1;
        threefry2x32(k.k0, k.k1, (uint32_t)i, (uint32_t)(i + n), y0, y1);
        buf[i] = y0;
        buf[n + i] = y1;
    }
    for (int j = 0; j < n; j++) { out[j].k0 = buf[2 * j]; out[j].k1 = buf[2 * j + 1]; }
}
#endif

// ---------------------------------------------------------------------------
// kernel_launch
// ---------------------------------------------------------------------------
extern "C" void kernel_launch(void* const* d_in, const int* in_sizes, int n_in,
                              void* d_out, int out_size) {
    (void)in_sizes; (void)n_in; (void)out_size;
    const float* v0 = (const float*)d_in[0];   // [B, V, 1] binary fp32
    const float* W  = (const float*)d_in[1];   // [H, V]
    const float* bb = (const float*)d_in[2];   // [V, 1]
    const float* cc = (const float*)d_in[3];   // [H, 1]

    float* out_v  = (float*)d_out;                              // [B, V] final v
    float* out_h  = out_v + (size_t)BATCH * VDIM;               // [B, H] final h
    float* out_h0 = out_h + (size_t)BATCH * HDIM;               // [B, H] h|v0

    // --- derive the 13 keys exactly as the reference does ---
    Key root{0u, 42u};
    Key keys[NITER + 1];
#if TF_PARTITIONABLE
    for (int i = 0; i <= NITER; i++) keys[i] = tf_key(root, (uint32_t)i);
#else
    legacy_split(root, NITER + 1, keys);
#endif
    Key kv[NITER + 1], kh[NITER + 1];
    for (int i = 1; i <= NITER; i++) {
#if TF_PARTITIONABLE
        kv[i] = tf_key(keys[i], 0u);
        kh[i] = tf_key(keys[i], 1u);
#else
        Key two[2];
        legacy_split(keys[i], 2, two);
        kv[i] = two[0]; kh[i] = two[1];
#endif
    }

    const uint32_t totH = (uint32_t)BATCH * HDIM;
    const uint32_t totV = (uint32_t)BATCH * VDIM;

    // H-step: out_h* = sample(sigmoid(W @ v + c))  -> GEMM [B,128] = [B,1024]x[1024,128]
    //   W stored [H=128, V=1024] = [N, K] row-major  -> BTRANS = true
    // V-step: out_v  = sample(sigmoid(W^T @ h + b)) -> GEMM [B,1024] = [B,128]x[128,1024]
    //   W stored [H=128, V=1024] = [K, N] row-major  -> BTRANS = false
    dim3 gridH(BATCH / 64, HDIM / 128);   // (512, 1)
    dim3 gridV(BATCH / 128, VDIM / 64);   // (256, 16)

    // h0 = sample(p(h|v0), keys[0])
    gemm_sigmoid_sample<64, 128, 32, 4, 8, true><<<gridH, 256>>>(
        v0, W, cc, out_h0, HDIM, VDIM, keys[0].k0, keys[0].k1, totH);

    const float* hcur = out_h0;
    for (int i = 1; i <= NITER; i++) {
        // v = sample(p(v|h), kv[i])
        gemm_sigmoid_sample<128, 64, 32, 8, 4, false><<<gridV, 256>>>(
            hcur, W, bb, out_v, VDIM, HDIM, kv[i].k0, kv[i].k1, totV);
        // h = sample(p(h|v), kh[i])
        gemm_sigmoid_sample<64, 128, 32, 4, 8, true><<<gridH, 256>>>(
            out_v, W, cc, out_h, HDIM, VDIM, kh[i].k0, kh[i].k1, totH);
        hcur = out_h;
    }
}

// round 6
// speedup vs baseline: 3.1696x; 3.1696x over previous
#include <cuda_runtime.h>
#include <cuda_bf16.h>
#include <cstdint>
#include <cmath>

// ---------------------------------------------------------------------------
// Problem constants
// ---------------------------------------------------------------------------
#define BATCH 32768
#define VDIM  1024
#define HDIM  128
#define NITER 4

// ---------------------------------------------------------------------------
// Threefry-2x32 (exact JAX rounds)
// ---------------------------------------------------------------------------
__host__ __device__ __forceinline__ uint32_t rotl32(uint32_t v, int s) {
    return (v << s) | (v >> (32 - s));
}

__host__ __device__ inline void threefry2x32(uint32_t k0, uint32_t k1,
                                             uint32_t x0, uint32_t x1,
                                             uint32_t &o0, uint32_t &o1) {
    const uint32_t k2 = k0 ^ k1 ^ 0x1BD11BDAu;
    x0 += k0; x1 += k1;
#define TF_ROUND(r) { x0 += x1; x1 = rotl32(x1, (r)); x1 ^= x0; }
    TF_ROUND(13) TF_ROUND(15) TF_ROUND(26) TF_ROUND(6)
    x0 += k1; x1 += k2 + 1u;
    TF_ROUND(17) TF_ROUND(29) TF_ROUND(16) TF_ROUND(24)
    x0 += k2; x1 += k0 + 2u;
    TF_ROUND(13) TF_ROUND(15) TF_ROUND(26) TF_ROUND(6)
    x0 += k0; x1 += k1 + 3u;
    TF_ROUND(17) TF_ROUND(29) TF_ROUND(16) TF_ROUND(24)
    x0 += k1; x1 += k2 + 4u;
    TF_ROUND(13) TF_ROUND(15) TF_ROUND(26) TF_ROUND(6)
    x0 += k2; x1 += k0 + 5u;
#undef TF_ROUND
    o0 = x0; o1 = x1;
}

// Partitionable 32-bit random bits: y0 ^ y1 of threefry(key, 0, idx).
__device__ __forceinline__ uint32_t jax_bits(uint32_t key0, uint32_t key1,
                                             uint32_t idx) {
    uint32_t y0, y1;
    threefry2x32(key0, key1, 0u, idx, y0, y1);
    return y0 ^ y1;
}

// sigmoid + exact-enough Bernoulli decision (fp64 slow path near the boundary)
__device__ __forceinline__ float sample_one(float x, uint32_t idx,
                                            uint32_t key0, uint32_t key1) {
    float p = 1.f / (1.f + expf(-x));
    uint32_t bits = jax_bits(key0, key1, idx);
    float u = __uint_as_float((bits >> 9) | 0x3f800000u) - 1.f;
    if (fabsf(u - p) > 1e-4f) {
        return (u < p) ? 1.f : 0.f;
    }
    double pd = 1.0 / (1.0 + exp(-(double)x));
    return (u < (float)pd) ? 1.f : 0.f;
}

// ---------------------------------------------------------------------------
// W splits in both orientations (bf16 x3: W = W1 + W2 + W3)
// ---------------------------------------------------------------------------
__device__ __nv_bfloat16 g_Whv[3][HDIM * VDIM];  // [h][v] K-major for H-step B
__device__ __nv_bfloat16 g_Wvh[3][VDIM * HDIM];  // [v][h] K-major for V-step B

__global__ void prep_w_kernel(const float* __restrict__ W) {
    int i = blockIdx.x * 256 + threadIdx.x;   // 0 .. 128*1024-1
    if (i >= HDIM * VDIM) return;
    int h = i >> 10;
    int v = i & 1023;
    float w = W[i];
    __nv_bfloat16 b1 = __float2bfloat16(w);
    float r1 = w - __bfloat162float(b1);
    __nv_bfloat16 b2 = __float2bfloat16(r1);
    float r2 = r1 - __bfloat162float(b2);
    __nv_bfloat16 b3 = __float2bfloat16(r2);
    g_Whv[0][i] = b1; g_Whv[1][i] = b2; g_Whv[2][i] = b3;
    int t = v * HDIM + h;
    g_Wvh[0][t] = b1; g_Wvh[1][t] = b2; g_Wvh[2][t] = b3;
}

// ---------------------------------------------------------------------------
// mma.sync / ldmatrix helpers (sm_80+ PTX, compiles under compute_103)
// ---------------------------------------------------------------------------
__device__ __forceinline__ void ldm_x4(uint32_t* r, uint32_t addr) {
    asm volatile(
        "ldmatrix.sync.aligned.m8n8.x4.shared.b16 {%0, %1, %2, %3}, [%4];"
        : "=r"(r[0]), "=r"(r[1]), "=r"(r[2]), "=r"(r[3])
        : "r"(addr));
}

__device__ __forceinline__ void mma16816(float* c, const uint32_t* a,
                                         const uint32_t* b) {
    asm volatile(
        "mma.sync.aligned.m16n8k16.row.col.f32.bf16.bf16.f32 "
        "{%0, %1, %2, %3}, {%4, %5, %6, %7}, {%8, %9}, {%0, %1, %2, %3};"
        : "+f"(c[0]), "+f"(c[1]), "+f"(c[2]), "+f"(c[3])
        : "r"(a[0]), "r"(a[1]), "r"(a[2]), "r"(a[3]), "r"(b[0]), "r"(b[1]));
}

// ---------------------------------------------------------------------------
// Fused HMMA GEMM -> sigmoid -> Bernoulli kernel.
//   D[128 x 128] per CTA; A [B, K] binary fp32 -> bf16; B = 3 bf16 splits of
//   W, K-major [Ntot, K]. acc accumulates over both K-chunks and splits.
// Warp layout: 8 warps = 4 (m) x 2 (n); warp tile 32m x 64n
//            = 2 (m16) x 8 (n8) mma tiles.
// ---------------------------------------------------------------------------
static constexpr int SSTR = 72;   // smem row stride in bf16 (144 B, 16B-aligned)

template <int K, bool HV>
__global__ __launch_bounds__(256, 2)
void rbm_step_mma(const float* __restrict__ A,
                  const float* __restrict__ bias,
                  float* __restrict__ out, int Ntot,
                  uint32_t key0, uint32_t key1) {
    __shared__ __nv_bfloat16 As[128 * SSTR];
    __shared__ __nv_bfloat16 Bs[128 * SSTR];

    const int tid  = threadIdx.x;
    const int wid  = tid >> 5;
    const int lane = tid & 31;
    const int warp_m = wid & 3;     // 0..3 -> 32-row slab
    const int warp_n = wid >> 2;    // 0..1 -> 64-col slab
    const int m0 = blockIdx.x * 128;
    const int n0 = blockIdx.y * 128;

    const uint32_t as_u = (uint32_t)__cvta_generic_to_shared(As);
    const uint32_t bs_u = (uint32_t)__cvta_generic_to_shared(Bs);

    float acc[2][8][4];
#pragma unroll
    for (int i = 0; i < 2; i++)
#pragma unroll
        for (int j = 0; j < 8; j++)
#pragma unroll
            for (int c = 0; c < 4; c++) acc[i][j][c] = 0.f;

    // ldmatrix lane-address components (same pattern for A and B)
    const int lrow8 = ((lane >> 3) & 1) * 8 + (lane & 7);  // A: row sel
    const int lcolA = (lane >> 4) * 8;                     // A: k sel
    const int lrowB = ((lane >> 4) & 1) * 8 + (lane & 7);  // B: n sel
    const int lcolB = ((lane >> 3) & 1) * 8;               // B: k sel

    for (int kc = 0; kc < K / 64; kc++) {
        __syncthreads();   // prior MMAs done reading As/Bs
        // ---- fill A tile [128 x 64], fp32 -> bf16 ----
#pragma unroll
        for (int it = 0; it < 4; it++) {
            int gid = tid + it * 256;            // 0..1023
            int row = gid >> 3;
            int g   = gid & 7;                   // 16B group
            const float* src = A + (size_t)(m0 + row) * K + kc * 64 + g * 8;
            float4 f0 = *reinterpret_cast<const float4*>(src);
            float4 f1 = *reinterpret_cast<const float4*>(src + 4);
            __nv_bfloat162 h0 = __float22bfloat162_rn(make_float2(f0.x, f0.y));
            __nv_bfloat162 h1 = __float22bfloat162_rn(make_float2(f0.z, f0.w));
            __nv_bfloat162 h2 = __float22bfloat162_rn(make_float2(f1.x, f1.y));
            __nv_bfloat162 h3 = __float22bfloat162_rn(make_float2(f1.z, f1.w));
            uint4 u;
            u.x = *reinterpret_cast<uint32_t*>(&h0);
            u.y = *reinterpret_cast<uint32_t*>(&h1);
            u.z = *reinterpret_cast<uint32_t*>(&h2);
            u.w = *reinterpret_cast<uint32_t*>(&h3);
            *reinterpret_cast<uint4*>(&As[row * SSTR + g * 8]) = u;
        }

#pragma unroll
        for (int s = 0; s < 3; s++) {
            if (s) __syncthreads();  // prior MMAs done reading Bs
            const __nv_bfloat16* Bk = HV ? g_Whv[s] : g_Wvh[s];
#pragma unroll
            for (int it = 0; it < 4; it++) {
                int gid = tid + it * 256;
                int row = gid >> 3;
                int g   = gid & 7;
                uint4 d = *reinterpret_cast<const uint4*>(
                    Bk + (size_t)(n0 + row) * K + kc * 64 + g * 8);
                *reinterpret_cast<uint4*>(&Bs[row * SSTR + g * 8]) = d;
            }
            __syncthreads();         // tiles visible

            // ---- 4 k16 steps over this [128 x 64] tile pair ----
#pragma unroll
            for (int k16 = 0; k16 < 4; k16++) {
                const int kb = k16 * 16;
                uint32_t afr[2][4];
#pragma unroll
                for (int tm = 0; tm < 2; tm++) {
                    int row = warp_m * 32 + tm * 16 + lrow8;
                    ldm_x4(afr[tm],
                           as_u + (uint32_t)(row * SSTR + kb + lcolA) * 2u);
                }
#pragma unroll
                for (int tp = 0; tp < 4; tp++) {     // pairs of n8 tiles
                    int nb = warp_n * 64 + tp * 16;
                    uint32_t bfr[4];
                    ldm_x4(bfr,
                           bs_u + (uint32_t)((nb + lrowB) * SSTR + kb + lcolB) * 2u);
                    mma16816(acc[0][tp * 2 + 0], afr[0], bfr + 0);
                    mma16816(acc[0][tp * 2 + 1], afr[0], bfr + 2);
                    mma16816(acc[1][tp * 2 + 0], afr[1], bfr + 0);
                    mma16816(acc[1][tp * 2 + 1], afr[1], bfr + 2);
                }
            }
        }
    }

    // ---- epilogue: bias + sigmoid + threefry-bernoulli, float2 stores ----
    const int mbase = m0 + warp_m * 32;
    const int nbase = n0 + warp_n * 64 + (lane & 3) * 2;
#pragma unroll
    for (int tm = 0; tm < 2; tm++) {
#pragma unroll
        for (int half = 0; half < 2; half++) {
            const int m = mbase + tm * 16 + (lane >> 2) + half * 8;
            const uint32_t mrow = (uint32_t)m * (uint32_t)Ntot;
#pragma unroll
            for (int tn = 0; tn < 8; tn++) {
                const int n = nbase + tn * 8;
                const float bn0 = __ldg(bias + n);
                const float bn1 = __ldg(bias + n + 1);
                float x0 = acc[tm][tn][half * 2 + 0] + bn0;
                float x1 = acc[tm][tn][half * 2 + 1] + bn1;
                float2 o;
                o.x = sample_one(x0, mrow + (uint32_t)n,     key0, key1);
                o.y = sample_one(x1, mrow + (uint32_t)n + 1, key0, key1);
                *reinterpret_cast<float2*>(out + mrow + (uint32_t)n) = o;
            }
        }
    }
}

// ---------------------------------------------------------------------------
// Host-side JAX key derivation
// ---------------------------------------------------------------------------
struct Key { uint32_t k0, k1; };

static inline Key tf_key(Key k, uint32_t lo) {
    Key r;
    threefry2x32(k.k0, k.k1, 0u, lo, r.k0, r.k1);
    return r;
}

// ---------------------------------------------------------------------------
// kernel_launch
// ---------------------------------------------------------------------------
extern "C" void kernel_launch(void* const* d_in, const int* in_sizes, int n_in,
                              void* d_out, int out_size) {
    (void)in_sizes; (void)n_in; (void)out_size;
    const float* v0 = (const float*)d_in[0];   // [B, V, 1] binary fp32
    const float* W  = (const float*)d_in[1];   // [H, V]
    const float* bb = (const float*)d_in[2];   // [V, 1]
    const float* cc = (const float*)d_in[3];   // [H, 1]

    float* out_v  = (float*)d_out;                        // [B, V] final v
    float* out_h  = out_v + (size_t)BATCH * VDIM;         // [B, H] final h
    float* out_h0 = out_h + (size_t)BATCH * HDIM;         // [B, H] h|v0

    // derive the 13 keys exactly as the reference does
    Key root{0u, 42u};
    Key keys[NITER + 1];
    for (int i = 0; i <= NITER; i++) keys[i] = tf_key(root, (uint32_t)i);
    Key kv[NITER + 1], kh[NITER + 1];
    for (int i = 1; i <= NITER; i++) {
        kv[i] = tf_key(keys[i], 0u);
        kh[i] = tf_key(keys[i], 1u);
    }

    // prep: W -> 3 bf16 splits in both orientations
    prep_w_kernel<<<(HDIM * VDIM + 255) / 256, 256>>>(W);

    // H-step: [B,128] = v[B,1024] @ Whv^T   (K=1024)
    // V-step: [B,1024] = h[B,128] @ Wvh^T   (K=128)
    dim3 gridH(BATCH / 128, HDIM / 128);   // (256, 1)
    dim3 gridV(BATCH / 128, VDIM / 128);   // (256, 8)

    rbm_step_mma<VDIM, true><<<gridH, 256>>>(
        v0, cc, out_h0, HDIM, keys[0].k0, keys[0].k1);

    const float* hcur = out_h0;
    for (int i = 1; i <= NITER; i++) {
        rbm_step_mma<HDIM, false><<<gridV, 256>>>(
            hcur, bb, out_v, VDIM, kv[i].k0, kv[i].k1);
        rbm_step_mma<VDIM, true><<<gridH, 256>>>(
            out_v, cc, out_h, HDIM, kh[i].k0, kh[i].k1);
        hcur = out_h;
    }
}

// round 7
// speedup vs baseline: 3.3721x; 1.0639x over previous
#include <cuda_runtime.h>
#include <cuda_bf16.h>
#include <cstdint>
#include <cmath>

// ---------------------------------------------------------------------------
// Problem constants
// ---------------------------------------------------------------------------
#define BATCH 32768
#define VDIM  1024
#define HDIM  128
#define NITER 4

// ---------------------------------------------------------------------------
// Threefry-2x32 (exact JAX rounds)
// ---------------------------------------------------------------------------
__host__ __device__ __forceinline__ uint32_t rotl32(uint32_t v, int s) {
    return (v << s) | (v >> (32 - s));
}

__host__ __device__ inline void threefry2x32(uint32_t k0, uint32_t k1,
                                             uint32_t x0, uint32_t x1,
                                             uint32_t &o0, uint32_t &o1) {
    const uint32_t k2 = k0 ^ k1 ^ 0x1BD11BDAu;
    x0 += k0; x1 += k1;
#define TF_ROUND(r) { x0 += x1; x1 = rotl32(x1, (r)); x1 ^= x0; }
    TF_ROUND(13) TF_ROUND(15) TF_ROUND(26) TF_ROUND(6)
    x0 += k1; x1 += k2 + 1u;
    TF_ROUND(17) TF_ROUND(29) TF_ROUND(16) TF_ROUND(24)
    x0 += k2; x1 += k0 + 2u;
    TF_ROUND(13) TF_ROUND(15) TF_ROUND(26) TF_ROUND(6)
    x0 += k0; x1 += k1 + 3u;
    TF_ROUND(17) TF_ROUND(29) TF_ROUND(16) TF_ROUND(24)
    x0 += k1; x1 += k2 + 4u;
    TF_ROUND(13) TF_ROUND(15) TF_ROUND(26) TF_ROUND(6)
    x0 += k2; x1 += k0 + 5u;
#undef TF_ROUND
    o0 = x0; o1 = x1;
}

// Partitionable 32-bit random bits: y0 ^ y1 of threefry(key, 0, idx).
__device__ __forceinline__ uint32_t jax_bits(uint32_t key0, uint32_t key1,
                                             uint32_t idx) {
    uint32_t y0, y1;
    threefry2x32(key0, key1, 0u, idx, y0, y1);
    return y0 ^ y1;
}

// sigmoid + exact-enough Bernoulli decision (fp64 slow path near the boundary)
__device__ __forceinline__ float sample_one(float x, uint32_t idx,
                                            uint32_t key0, uint32_t key1) {
    float p = 1.f / (1.f + expf(-x));
    uint32_t bits = jax_bits(key0, key1, idx);
    float u = __uint_as_float((bits >> 9) | 0x3f800000u) - 1.f;
    if (fabsf(u - p) > 1e-4f) {
        return (u < p) ? 1.f : 0.f;
    }
    double pd = 1.0 / (1.0 + exp(-(double)x));
    return (u < (float)pd) ? 1.f : 0.f;
}

// ---------------------------------------------------------------------------
// W splits in both orientations (bf16 x3: W = W1 + W2 + W3) + bf16 sample bufs
// ---------------------------------------------------------------------------
__device__ __nv_bfloat16 g_Whv[3][HDIM * VDIM];  // [h][v] K-major for H-step B
__device__ __nv_bfloat16 g_Wvh[3][VDIM * HDIM];  // [v][h] K-major for V-step B
__device__ __nv_bfloat16 g_hbf[BATCH * HDIM];    // latest h as bf16
__device__ __nv_bfloat16 g_vbf[BATCH * VDIM];    // latest v as bf16

__global__ void prep_w_kernel(const float* __restrict__ W) {
    int i = blockIdx.x * 256 + threadIdx.x;   // 0 .. 128*1024-1
    if (i >= HDIM * VDIM) return;
    int h = i >> 10;
    int v = i & 1023;
    float w = W[i];
    __nv_bfloat16 b1 = __float2bfloat16(w);
    float r1 = w - __bfloat162float(b1);
    __nv_bfloat16 b2 = __float2bfloat16(r1);
    float r2 = r1 - __bfloat162float(b2);
    __nv_bfloat16 b3 = __float2bfloat16(r2);
    g_Whv[0][i] = b1; g_Whv[1][i] = b2; g_Whv[2][i] = b3;
    int t = v * HDIM + h;
    g_Wvh[0][t] = b1; g_Wvh[1][t] = b2; g_Wvh[2][t] = b3;
}

// ---------------------------------------------------------------------------
// mma.sync / ldmatrix helpers (sm_80+ PTX, compiles under compute_103)
// ---------------------------------------------------------------------------
__device__ __forceinline__ void ldm_x4(uint32_t* r, uint32_t addr) {
    asm volatile(
        "ldmatrix.sync.aligned.m8n8.x4.shared.b16 {%0, %1, %2, %3}, [%4];"
        : "=r"(r[0]), "=r"(r[1]), "=r"(r[2]), "=r"(r[3])
        : "r"(addr));
}

__device__ __forceinline__ void mma16816(float* c, const uint32_t* a,
                                         const uint32_t* b) {
    asm volatile(
        "mma.sync.aligned.m16n8k16.row.col.f32.bf16.bf16.f32 "
        "{%0, %1, %2, %3}, {%4, %5, %6, %7}, {%8, %9}, {%0, %1, %2, %3};"
        : "+f"(c[0]), "+f"(c[1]), "+f"(c[2]), "+f"(c[3])
        : "r"(a[0]), "r"(a[1]), "r"(a[2]), "r"(a[3]), "r"(b[0]), "r"(b[1]));
}

// ---------------------------------------------------------------------------
// Fused HMMA GEMM -> sigmoid -> Bernoulli kernel.
//   D[128 x 128] per CTA; A [B, K] binary (fp32 or bf16); B = 3 bf16 splits
//   of W, K-major [Ntot, K], all resident in smem per K-chunk.
//   acc order: split outer, k16 inner (bit-identical to the 2-sync version).
// Warp layout: 8 warps = 4 (m) x 2 (n); warp tile 32m x 64n.
// ---------------------------------------------------------------------------
static constexpr int SSTR = 72;   // smem row stride in bf16 (144 B)
static constexpr int TILE_ELEMS = 128 * SSTR;            // per split / per A
static constexpr uint32_t BSPLIT_BYTES = TILE_ELEMS * 2; // bytes per B split
static constexpr int SMEM_DYN = 4 * TILE_ELEMS * 2;      // A + 3 B = 73728 B

template <int K, bool HV, bool ABF16>
__global__ __launch_bounds__(256, 2)
void rbm_step_mma(const void* __restrict__ Ain,
                  const float* __restrict__ bias,
                  float* __restrict__ out,
                  __nv_bfloat16* __restrict__ out_bf,
                  int Ntot, uint32_t key0, uint32_t key1) {
    extern __shared__ __nv_bfloat16 dsm[];
    __nv_bfloat16* const As = dsm;
    __nv_bfloat16* const Bs = dsm + TILE_ELEMS;

    const int tid  = threadIdx.x;
    const int wid  = tid >> 5;
    const int lane = tid & 31;
    const int warp_m = wid & 3;     // 0..3 -> 32-row slab
    const int warp_n = wid >> 2;    // 0..1 -> 64-col slab
    const int m0 = blockIdx.x * 128;
    const int n0 = blockIdx.y * 128;

    const uint32_t as_u = (uint32_t)__cvta_generic_to_shared(As);
    const uint32_t bs_u = (uint32_t)__cvta_generic_to_shared(Bs);

    float acc[2][8][4];
#pragma unroll
    for (int i = 0; i < 2; i++)
#pragma unroll
        for (int j = 0; j < 8; j++)
#pragma unroll
            for (int c = 0; c < 4; c++) acc[i][j][c] = 0.f;

    // ldmatrix lane-address components
    const int lrow8 = ((lane >> 3) & 1) * 8 + (lane & 7);  // A: row sel
    const int lcolA = (lane >> 4) * 8;                     // A: k sel
    const int lrowB = ((lane >> 4) & 1) * 8 + (lane & 7);  // B: n sel
    const int lcolB = ((lane >> 3) & 1) * 8;               // B: k sel

    for (int kc = 0; kc < K / 64; kc++) {
        __syncthreads();   // prior MMAs done reading As/Bs
        // ---- fill A tile [128 x 64] ----
        if (ABF16) {
            const __nv_bfloat16* Af = (const __nv_bfloat16*)Ain;
#pragma unroll
            for (int it = 0; it < 4; it++) {
                int gid = tid + it * 256;
                int row = gid >> 3;
                int g   = gid & 7;
                uint4 d = *reinterpret_cast<const uint4*>(
                    Af + (size_t)(m0 + row) * K + kc * 64 + g * 8);
                *reinterpret_cast<uint4*>(&As[row * SSTR + g * 8]) = d;
            }
        } else {
            const float* Af = (const float*)Ain;
#pragma unroll
            for (int it = 0; it < 4; it++) {
                int gid = tid + it * 256;
                int row = gid >> 3;
                int g   = gid & 7;
                const float* src = Af + (size_t)(m0 + row) * K + kc * 64 + g * 8;
                float4 f0 = *reinterpret_cast<const float4*>(src);
                float4 f1 = *reinterpret_cast<const float4*>(src + 4);
                __nv_bfloat162 h0 = __float22bfloat162_rn(make_float2(f0.x, f0.y));
                __nv_bfloat162 h1 = __float22bfloat162_rn(make_float2(f0.z, f0.w));
                __nv_bfloat162 h2 = __float22bfloat162_rn(make_float2(f1.x, f1.y));
                __nv_bfloat162 h3 = __float22bfloat162_rn(make_float2(f1.z, f1.w));
                uint4 u;
                u.x = *reinterpret_cast<uint32_t*>(&h0);
                u.y = *reinterpret_cast<uint32_t*>(&h1);
                u.z = *reinterpret_cast<uint32_t*>(&h2);
                u.w = *reinterpret_cast<uint32_t*>(&h3);
                *reinterpret_cast<uint4*>(&As[row * SSTR + g * 8]) = u;
            }
        }
        // ---- fill all 3 B splits [128 x 64] each ----
#pragma unroll
        for (int s = 0; s < 3; s++) {
            const __nv_bfloat16* Bk = HV ? g_Whv[s] : g_Wvh[s];
#pragma unroll
            for (int it = 0; it < 4; it++) {
                int gid = tid + it * 256;
                int row = gid >> 3;
                int g   = gid & 7;
                uint4 d = *reinterpret_cast<const uint4*>(
                    Bk + (size_t)(n0 + row) * K + kc * 64 + g * 8);
                *reinterpret_cast<uint4*>(
                    &Bs[s * TILE_ELEMS + row * SSTR + g * 8]) = d;
            }
        }
        __syncthreads();   // tiles visible

        // ---- MMA: split outer, k16 inner (order == previous version) ----
#pragma unroll
        for (int s = 0; s < 3; s++) {
            const uint32_t bsp = bs_u + (uint32_t)s * BSPLIT_BYTES;
#pragma unroll
            for (int k16 = 0; k16 < 4; k16++) {
                const int kb = k16 * 16;
                uint32_t afr[2][4];
#pragma unroll
                for (int tm = 0; tm < 2; tm++) {
                    int row = warp_m * 32 + tm * 16 + lrow8;
                    ldm_x4(afr[tm],
                           as_u + (uint32_t)(row * SSTR + kb + lcolA) * 2u);
                }
#pragma unroll
                for (int tp = 0; tp < 4; tp++) {     // pairs of n8 tiles
                    int nb = warp_n * 64 + tp * 16;
                    uint32_t bfr[4];
                    ldm_x4(bfr,
                           bsp + (uint32_t)((nb + lrowB) * SSTR + kb + lcolB) * 2u);
                    mma16816(acc[0][tp * 2 + 0], afr[0], bfr + 0);
                    mma16816(acc[0][tp * 2 + 1], afr[0], bfr + 2);
                    mma16816(acc[1][tp * 2 + 0], afr[1], bfr + 0);
                    mma16816(acc[1][tp * 2 + 1], afr[1], bfr + 2);
                }
            }
        }
    }

    // ---- epilogue: bias + sigmoid + threefry-bernoulli; fp32 + bf16 out ----
    const int mbase = m0 + warp_m * 32;
    const int nbase = n0 + warp_n * 64 + (lane & 3) * 2;
#pragma unroll
    for (int tm = 0; tm < 2; tm++) {
#pragma unroll
        for (int half = 0; half < 2; half++) {
            const int m = mbase + tm * 16 + (lane >> 2) + half * 8;
            const uint32_t mrow = (uint32_t)m * (uint32_t)Ntot;
#pragma unroll
            for (int tn = 0; tn < 8; tn++) {
                const int n = nbase + tn * 8;
                const float bn0 = __ldg(bias + n);
                const float bn1 = __ldg(bias + n + 1);
                float x0 = acc[tm][tn][half * 2 + 0] + bn0;
                float x1 = acc[tm][tn][half * 2 + 1] + bn1;
                float2 o;
                o.x = sample_one(x0, mrow + (uint32_t)n,     key0, key1);
                o.y = sample_one(x1, mrow + (uint32_t)n + 1, key0, key1);
                *reinterpret_cast<float2*>(out + mrow + (uint32_t)n) = o;
                __nv_bfloat162 ob = __floats2bfloat162_rn(o.x, o.y);
                *reinterpret_cast<__nv_bfloat162*>(out_bf + mrow + (uint32_t)n) = ob;
            }
        }
    }
}

// ---------------------------------------------------------------------------
// Host-side JAX key derivation
// ---------------------------------------------------------------------------
struct Key { uint32_t k0, k1; };

static inline Key tf_key(Key k, uint32_t lo) {
    Key r;
    threefry2x32(k.k0, k.k1, 0u, lo, r.k0, r.k1);
    return r;
}

// ---------------------------------------------------------------------------
// kernel_launch
// ---------------------------------------------------------------------------
extern "C" void kernel_launch(void* const* d_in, const int* in_sizes, int n_in,
                              void* d_out, int out_size) {
    (void)in_sizes; (void)n_in; (void)out_size;
    const float* v0 = (const float*)d_in[0];   // [B, V, 1] binary fp32
    const float* W  = (const float*)d_in[1];   // [H, V]
    const float* bb = (const float*)d_in[2];   // [V, 1]
    const float* cc = (const float*)d_in[3];   // [H, 1]

    float* out_v  = (float*)d_out;                        // [B, V] final v
    float* out_h  = out_v + (size_t)BATCH * VDIM;         // [B, H] final h
    float* out_h0 = out_h + (size_t)BATCH * HDIM;         // [B, H] h|v0

    // derive the 13 keys exactly as the reference does
    Key root{0u, 42u};
    Key keys[NITER + 1];
    for (int i = 0; i <= NITER; i++) keys[i] = tf_key(root, (uint32_t)i);
    Key kv[NITER + 1], kh[NITER + 1];
    for (int i = 1; i <= NITER; i++) {
        kv[i] = tf_key(keys[i], 0u);
        kh[i] = tf_key(keys[i], 1u);
    }

    // raise dynamic smem limit (idempotent host-side attribute sets)
    cudaFuncSetAttribute(rbm_step_mma<VDIM, true,  false>,
                         cudaFuncAttributeMaxDynamicSharedMemorySize, SMEM_DYN);
    cudaFuncSetAttribute(rbm_step_mma<VDIM, true,  true>,
                         cudaFuncAttributeMaxDynamicSharedMemorySize, SMEM_DYN);
    cudaFuncSetAttribute(rbm_step_mma<HDIM, false, true>,
                         cudaFuncAttributeMaxDynamicSharedMemorySize, SMEM_DYN);

    // scratch bf16 buffers
    __nv_bfloat16* hbf;
    __nv_bfloat16* vbf;
    cudaGetSymbolAddress((void**)&hbf, g_hbf);
    cudaGetSymbolAddress((void**)&vbf, g_vbf);

    // prep: W -> 3 bf16 splits in both orientations
    prep_w_kernel<<<(HDIM * VDIM + 255) / 256, 256>>>(W);

    // H-step: [B,128] = v[B,1024] @ Whv^T   (K=1024)
    // V-step: [B,1024] = h[B,128] @ Wvh^T   (K=128)
    dim3 gridH(BATCH / 128, HDIM / 128);   // (256, 1)
    dim3 gridV(BATCH / 128, VDIM / 128);   // (256, 8)

    rbm_step_mma<VDIM, true, false><<<gridH, 256, SMEM_DYN>>>(
        v0, cc, out_h0, hbf, HDIM, keys[0].k0, keys[0].k1);

    for (int i = 1; i <= NITER; i++) {
        rbm_step_mma<HDIM, false, true><<<gridV, 256, SMEM_DYN>>>(
            hbf, bb, out_v, vbf, VDIM, kv[i].k0, kv[i].k1);
        rbm_step_mma<VDIM, true, true><<<gridH, 256, SMEM_DYN>>>(
            vbf, cc, out_h, hbf, HDIM, kh[i].k0, kh[i].k1);
    }
}